// round 10
// baseline (speedup 1.0000x reference)
#include <cuda_runtime.h>
#include <cuda_bf16.h>
#include <cstdint>
#include <cstddef>

#define EMBED   1024
#define S_LEN   2048
#define BATCH   4
#define HEADS   16
#define HDIM    64
#define QKV_DIM 3072
#define MTOT    8192          // BATCH * S_LEN

// ---------------------------------------------------------------------------
// Scratch (device globals; allocation-free rule)
// ---------------------------------------------------------------------------
__device__ __align__(128) float g_wqr[(size_t)QKV_DIM * EMBED];  // W_qkv tf32-rounded
__device__ __align__(128) float g_wor[(size_t)EMBED * EMBED];    // W_out tf32-rounded
__device__ __align__(128) float g_att[(size_t)MTOT * EMBED];     // attn out (tf32-rounded)
// head-contiguous attention operands [B*H, S, 64] bf16
__device__ __align__(128) __nv_bfloat16 g_Qb[(size_t)MTOT * EMBED];
__device__ __align__(128) __nv_bfloat16 g_Kb[(size_t)MTOT * EMBED];
__device__ __align__(128) __nv_bfloat16 g_Vh[(size_t)MTOT * EMBED];
__device__ __align__(128) __nv_bfloat16 g_Vl[(size_t)MTOT * EMBED];

// ---------------------------------------------------------------------------
__device__ __forceinline__ uint32_t smem_u32(const void* p) {
    uint32_t a;
    asm("{ .reg .u64 t; cvta.to.shared.u64 t, %1; cvt.u32.u64 %0, t; }" : "=r"(a) : "l"(p));
    return a;
}
__device__ __forceinline__ uint32_t swz(uint32_t off) {
    return off ^ ((off >> 3) & 0x70);
}
__device__ __forceinline__ void ldsm_x4(uint32_t* r, uint32_t addr) {
    asm volatile("ldmatrix.sync.aligned.m8n8.x4.shared.b16 {%0,%1,%2,%3}, [%4];"
                 : "=r"(r[0]), "=r"(r[1]), "=r"(r[2]), "=r"(r[3]) : "r"(addr));
}
__device__ __forceinline__ void ldsm_x4_t(uint32_t* r, uint32_t addr) {
    asm volatile("ldmatrix.sync.aligned.m8n8.x4.trans.shared.b16 {%0,%1,%2,%3}, [%4];"
                 : "=r"(r[0]), "=r"(r[1]), "=r"(r[2]), "=r"(r[3]) : "r"(addr));
}
__device__ __forceinline__ void mma_bf16(float* d, const uint32_t* a,
                                         uint32_t b0, uint32_t b1) {
    asm volatile(
        "mma.sync.aligned.m16n8k16.row.col.f32.bf16.bf16.f32 "
        "{%0,%1,%2,%3}, {%4,%5,%6,%7}, {%8,%9}, {%0,%1,%2,%3};"
        : "+f"(d[0]), "+f"(d[1]), "+f"(d[2]), "+f"(d[3])
        : "r"(a[0]), "r"(a[1]), "r"(a[2]), "r"(a[3]), "r"(b0), "r"(b1));
}
__device__ __forceinline__ void mma_tf32(float* d, const uint32_t* a,
                                         uint32_t b0, uint32_t b1) {
    asm volatile(
        "mma.sync.aligned.m16n8k8.row.col.f32.tf32.tf32.f32 "
        "{%0,%1,%2,%3}, {%4,%5,%6,%7}, {%8,%9}, {%0,%1,%2,%3};"
        : "+f"(d[0]), "+f"(d[1]), "+f"(d[2]), "+f"(d[3])
        : "r"(a[0]), "r"(a[1]), "r"(a[2]), "r"(a[3]), "r"(b0), "r"(b1));
}
__device__ __forceinline__ float rna_tf32(float x) {
    uint32_t r;
    asm("cvt.rna.tf32.f32 %0, %1;" : "=r"(r) : "f"(x));
    return __uint_as_float(r);
}

// ---------------------------------------------------------------------------
// tf32 pre-rounding of the two weight matrices only (X uses hw truncation)
// ---------------------------------------------------------------------------
#define N4_WQ (QKV_DIM * EMBED / 4)
#define N4_WO (EMBED * EMBED / 4)
__global__ void round_wts(const float* __restrict__ Wq, float* __restrict__ wqr,
                          const float* __restrict__ Wo, float* __restrict__ wor)
{
    int i = blockIdx.x * blockDim.x + threadIdx.x;
    const float4* src; float4* dst; int j;
    if (i < N4_WQ)             { src = (const float4*)Wq; dst = (float4*)wqr; j = i; }
    else if (i < N4_WQ + N4_WO){ src = (const float4*)Wo; dst = (float4*)wor; j = i - N4_WQ; }
    else return;
    float4 v = src[j];
    v.x = rna_tf32(v.x); v.y = rna_tf32(v.y);
    v.z = rna_tf32(v.z); v.w = rna_tf32(v.w);
    dst[j] = v;
}

// ---------------------------------------------------------------------------
// tf32 GEMM mainloop. 256x128 CTA tile, BK=32 floats (128B rows, SW128),
// 4-stage cp.async, 8 warps 4(m) x 2(n), warp tile 64x64.
// ---------------------------------------------------------------------------
#define GK         1024
#define BKF        32
#define NITF       (GK / BKF)          // 32
#define AT_B       32768               // A: 256 rows * 128 B
#define BT_B       16384               // B: 128 rows * 128 B
#define STAGE_B    (AT_B + BT_B)       // 48 KB
#define GSTAGES    4
#define GEMM_SMEM  (GSTAGES * STAGE_B) // 192 KB

__device__ __forceinline__ void fill_stage_f(uint32_t sb, int s, int c, int tid,
                                             const float* __restrict__ A,
                                             const float* __restrict__ B,
                                             int m0, int n0) {
    const uint32_t stage = sb + s * STAGE_B;
#pragma unroll
    for (int i = 0; i < 12; i++) {
        int seg = i * 256 + tid;        // 0..3071
        int r   = seg >> 3;             // 0..383 (0..255 = A, 256..383 = B)
        int sc  = seg & 7;
        const float* src;
        uint32_t d;
        if (r < 256) {
            src = A + (size_t)(m0 + r) * GK;
            d   = stage + swz((uint32_t)(r * 128 + sc * 16));
        } else {
            int rb = r - 256;
            src = B + (size_t)(n0 + rb) * GK;
            d   = stage + AT_B + swz((uint32_t)(rb * 128 + sc * 16));
        }
        const char* g = (const char*)(src + c * BKF) + sc * 16;
        asm volatile("cp.async.cg.shared.global [%0], [%1], 16;" :: "r"(d), "l"(g));
    }
}

__device__ __forceinline__ void gemm_mainloop(uint32_t sb,
                                              const float* __restrict__ A,
                                              const float* __restrict__ B,
                                              int m0, int n0, int tid,
                                              int wm, int wn,
                                              float (&acc)[4][8][4])
{
#pragma unroll
    for (int mf = 0; mf < 4; mf++)
#pragma unroll
        for (int nf = 0; nf < 8; nf++)
#pragma unroll
            for (int k = 0; k < 4; k++) acc[mf][nf][k] = 0.f;

    const int lid = tid & 31;
    const uint32_t lrow = (uint32_t)(lid & 15) * 128;
    const uint32_t lseg = (uint32_t)(lid >> 4) * 16;

    fill_stage_f(sb, 0, 0, tid, A, B, m0, n0);
    asm volatile("cp.async.commit_group;");
    fill_stage_f(sb, 1, 1, tid, A, B, m0, n0);
    asm volatile("cp.async.commit_group;");
    fill_stage_f(sb, 2, 2, tid, A, B, m0, n0);
    asm volatile("cp.async.commit_group;");

    for (int c = 0; c < NITF; c++) {
        asm volatile("cp.async.wait_group 2;");
        __syncthreads();
        const int cn = c + 3;
        if (cn < NITF) fill_stage_f(sb, cn % GSTAGES, cn, tid, A, B, m0, n0);
        asm volatile("cp.async.commit_group;");

        const uint32_t aBase = sb + (c % GSTAGES) * STAGE_B;
        const uint32_t bBase = aBase + AT_B;

#pragma unroll
        for (int ks = 0; ks < 4; ks++) {
            const uint32_t koff = (uint32_t)ks * 32 + lseg;
            uint32_t afr[4][4], bfr[4][4];
#pragma unroll
            for (int mf = 0; mf < 4; mf++)
                ldsm_x4(afr[mf], aBase + swz((uint32_t)(wm * 64 + mf * 16) * 128 + lrow + koff));
#pragma unroll
            for (int nh = 0; nh < 4; nh++)
                ldsm_x4(bfr[nh], bBase + swz((uint32_t)(wn * 64 + nh * 16) * 128 + lrow + koff));
#pragma unroll
            for (int mf = 0; mf < 4; mf++)
#pragma unroll
                for (int nf = 0; nf < 8; nf++)
                    mma_tf32(acc[mf][nf], afr[mf],
                             bfr[nf >> 1][nf & 1], bfr[nf >> 1][2 + (nf & 1)]);
        }
    }
    __syncthreads();
}

// Projection 1: QKV GEMM, fused epilogue -> Qb (scaled) / Kb / Vh / Vl bf16
__global__ __launch_bounds__(256)
void gemm_qkv_fused(const float* __restrict__ A, const float* __restrict__ B,
                    const float* __restrict__ bias,
                    __nv_bfloat16* __restrict__ Qb, __nv_bfloat16* __restrict__ Kb,
                    __nv_bfloat16* __restrict__ Vh, __nv_bfloat16* __restrict__ Vl)
{
    extern __shared__ char smem[];
    const uint32_t sb = smem_u32(smem);
    const int tid = threadIdx.x, wid = tid >> 5, lid = tid & 31;
    const int wm = wid >> 1, wn = wid & 1;
    const int m0 = blockIdx.y * 256;
    const int n0 = blockIdx.x * 128;

    float acc[4][8][4];
    gemm_mainloop(sb, A, B, m0, n0, tid, wm, wn, acc);

#pragma unroll
    for (int mf = 0; mf < 4; mf++) {
        const int row = m0 + wm * 64 + mf * 16 + (lid >> 2);
#pragma unroll
        for (int nf = 0; nf < 8; nf++) {
            const int col  = n0 + wn * 64 + nf * 8 + (lid & 3) * 2;
            const int part = col >> 10;
            const int hd   = col & 1023;
            const int h = hd >> 6, d = hd & 63;
            float2 bv = *(const float2*)(bias + col);
#pragma unroll
            for (int rr = 0; rr < 2; rr++) {
                const int r = row + rr * 8;
                const size_t o = ((size_t)((r >> 11) * HEADS + h) * S_LEN + (r & 2047)) * HDIM + d;
                float x0 = acc[mf][nf][rr * 2]     + bv.x;
                float x1 = acc[mf][nf][rr * 2 + 1] + bv.y;
                if (part == 0) {
                    *(__nv_bfloat162*)(Qb + o) =
                        __float22bfloat162_rn(make_float2(x0 * 0.125f, x1 * 0.125f));
                } else if (part == 1) {
                    *(__nv_bfloat162*)(Kb + o) =
                        __float22bfloat162_rn(make_float2(x0, x1));
                } else {
                    __nv_bfloat162 hi = __float22bfloat162_rn(make_float2(x0, x1));
                    float2 f = __bfloat1622float2(hi);
                    *(__nv_bfloat162*)(Vh + o) = hi;
                    *(__nv_bfloat162*)(Vl + o) =
                        __float22bfloat162_rn(make_float2(x0 - f.x, x1 - f.y));
                }
            }
        }
    }
}

// Projection 2: generic fp32-out GEMM + bias
__global__ __launch_bounds__(256)
void gemm_tf32_mma(const float* __restrict__ A, const float* __restrict__ B,
                   const float* __restrict__ bias, float* __restrict__ C, int N)
{
    extern __shared__ char smem[];
    const uint32_t sb = smem_u32(smem);
    const int tid = threadIdx.x, wid = tid >> 5, lid = tid & 31;
    const int wm = wid >> 1, wn = wid & 1;
    const int m0 = blockIdx.y * 256;
    const int n0 = blockIdx.x * 128;

    float acc[4][8][4];
    gemm_mainloop(sb, A, B, m0, n0, tid, wm, wn, acc);

#pragma unroll
    for (int mf = 0; mf < 4; mf++) {
        const int row = m0 + wm * 64 + mf * 16 + (lid >> 2);
#pragma unroll
        for (int nf = 0; nf < 8; nf++) {
            const int col = n0 + wn * 64 + nf * 8 + (lid & 3) * 2;
            float2 bv = *(const float2*)(bias + col);
            float2 v0 = make_float2(acc[mf][nf][0] + bv.x, acc[mf][nf][1] + bv.y);
            float2 v1 = make_float2(acc[mf][nf][2] + bv.x, acc[mf][nf][3] + bv.y);
            *(float2*)(C + (size_t)row * N + col)       = v0;
            *(float2*)(C + (size_t)(row + 8) * N + col) = v1;
        }
    }
}

// ---------------------------------------------------------------------------
// Tensor-core flash attention (bf16 QK, hi/lo-split PV). Frozen from round 9.
// ---------------------------------------------------------------------------
#define ATT_STAGE_B 24576
#define ATT_SMEM    (16384 + 3 * ATT_STAGE_B)
#define NKV         (S_LEN / 64)

__global__ __launch_bounds__(256, 2)
void attn_tc(const __nv_bfloat16* __restrict__ Qb, const __nv_bfloat16* __restrict__ Kb,
             const __nv_bfloat16* __restrict__ Vh, const __nv_bfloat16* __restrict__ Vl,
             float* __restrict__ outf)
{
    extern __shared__ char smem[];
    const uint32_t sb = smem_u32(smem);
    const int tid = threadIdx.x, wid = tid >> 5, lid = tid & 31;
    const int q0 = blockIdx.x * 128;
    const int bh = blockIdx.y;
    const size_t hb = (size_t)bh * S_LEN * HDIM;

    {
        const char* qg = (const char*)(Qb + hb + (size_t)q0 * HDIM);
        for (int i = tid; i < 1024; i += 256) {
            uint32_t d = sb + swz((uint32_t)i * 16);
            asm volatile("cp.async.cg.shared.global [%0], [%1], 16;" :: "r"(d), "l"(qg + i * 16));
        }
        asm volatile("cp.async.commit_group;");
    }
    auto load_kv = [&](int stage, int t) {
        const uint32_t st = sb + 16384 + stage * ATT_STAGE_B;
        const char* kg = (const char*)(Kb + hb + (size_t)t * 64 * HDIM);
        const char* hg = (const char*)(Vh + hb + (size_t)t * 64 * HDIM);
        const char* lg = (const char*)(Vl + hb + (size_t)t * 64 * HDIM);
        for (int i = tid; i < 512; i += 256) {
            uint32_t o = swz((uint32_t)i * 16);
            asm volatile("cp.async.cg.shared.global [%0], [%1], 16;" :: "r"(st + o),         "l"(kg + i * 16));
            asm volatile("cp.async.cg.shared.global [%0], [%1], 16;" :: "r"(st + 8192 + o),  "l"(hg + i * 16));
            asm volatile("cp.async.cg.shared.global [%0], [%1], 16;" :: "r"(st + 16384 + o), "l"(lg + i * 16));
        }
    };
    load_kv(0, 0);
    asm volatile("cp.async.commit_group;");
    load_kv(1, 1);
    asm volatile("cp.async.commit_group;");

    asm volatile("cp.async.wait_group 2;");
    __syncthreads();

    const uint32_t lrow = (uint32_t)(lid & 15) * 128;
    const uint32_t lseg = (uint32_t)(lid >> 4) * 16;

    uint32_t qfr[4][4];
#pragma unroll
    for (int ks = 0; ks < 4; ks++)
        ldsm_x4(qfr[ks], sb + swz((uint32_t)(wid * 16) * 128 + lrow + ks * 32 + lseg));

    float o_acc[8][4];
#pragma unroll
    for (int nf = 0; nf < 8; nf++)
#pragma unroll
        for (int k = 0; k < 4; k++) o_acc[nf][k] = 0.f;
    float m0 = -1e30f, m8 = -1e30f, l0 = 0.f, l8 = 0.f;

    for (int t = 0; t < NKV; t++) {
        asm volatile("cp.async.wait_group 1;");
        __syncthreads();
        if (t + 2 < NKV) load_kv((t + 2) % 3, t + 2);
        asm volatile("cp.async.commit_group;");

        const uint32_t st = sb + 16384 + (t % 3) * ATT_STAGE_B;

        float sfr[8][4];
#pragma unroll
        for (int nf = 0; nf < 8; nf++)
#pragma unroll
            for (int k = 0; k < 4; k++) sfr[nf][k] = 0.f;
#pragma unroll
        for (int ks = 0; ks < 4; ks++) {
            uint32_t bfr[4][4];
#pragma unroll
            for (int nh = 0; nh < 4; nh++)
                ldsm_x4(bfr[nh], st + swz((uint32_t)(nh * 16) * 128 + lrow + ks * 32 + lseg));
#pragma unroll
            for (int nf = 0; nf < 8; nf++)
                mma_bf16(sfr[nf], qfr[ks],
                         bfr[nf >> 1][nf & 1], bfr[nf >> 1][2 + (nf & 1)]);
        }

        float mx0 = -1e30f, mx8 = -1e30f;
#pragma unroll
        for (int j = 0; j < 8; j++) {
            mx0 = fmaxf(mx0, fmaxf(sfr[j][0], sfr[j][1]));
            mx8 = fmaxf(mx8, fmaxf(sfr[j][2], sfr[j][3]));
        }
        mx0 = fmaxf(mx0, __shfl_xor_sync(0xffffffffu, mx0, 1));
        mx0 = fmaxf(mx0, __shfl_xor_sync(0xffffffffu, mx0, 2));
        mx8 = fmaxf(mx8, __shfl_xor_sync(0xffffffffu, mx8, 1));
        mx8 = fmaxf(mx8, __shfl_xor_sync(0xffffffffu, mx8, 2));
        const float mn0 = fmaxf(m0, mx0), mn8 = fmaxf(m8, mx8);
        const float a0 = __expf(m0 - mn0), a8 = __expf(m8 - mn8);
        m0 = mn0; m8 = mn8;

        uint32_t pr0[8], pr8[8], qr0[8], qr8[8];
        float s0 = 0.f, s8 = 0.f;
#pragma unroll
        for (int j = 0; j < 8; j++) {
            float p0 = __expf(sfr[j][0] - mn0);
            float p1 = __expf(sfr[j][1] - mn0);
            float p2 = __expf(sfr[j][2] - mn8);
            float p3 = __expf(sfr[j][3] - mn8);
            s0 += p0 + p1; s8 += p2 + p3;
            __nv_bfloat162 h01 = __float22bfloat162_rn(make_float2(p0, p1));
            __nv_bfloat162 h23 = __float22bfloat162_rn(make_float2(p2, p3));
            float2 f01 = __bfloat1622float2(h01);
            float2 f23 = __bfloat1622float2(h23);
            __nv_bfloat162 l01 = __float22bfloat162_rn(make_float2(p0 - f01.x, p1 - f01.y));
            __nv_bfloat162 l23 = __float22bfloat162_rn(make_float2(p2 - f23.x, p3 - f23.y));
            pr0[j] = *(uint32_t*)&h01; pr8[j] = *(uint32_t*)&h23;
            qr0[j] = *(uint32_t*)&l01; qr8[j] = *(uint32_t*)&l23;
        }
        s0 += __shfl_xor_sync(0xffffffffu, s0, 1);
        s0 += __shfl_xor_sync(0xffffffffu, s0, 2);
        s8 += __shfl_xor_sync(0xffffffffu, s8, 1);
        s8 += __shfl_xor_sync(0xffffffffu, s8, 2);
        l0 = l0 * a0 + s0;
        l8 = l8 * a8 + s8;
#pragma unroll
        for (int nf = 0; nf < 8; nf++) {
            o_acc[nf][0] *= a0; o_acc[nf][1] *= a0;
            o_acc[nf][2] *= a8; o_acc[nf][3] *= a8;
        }

#pragma unroll
        for (int ks = 0; ks < 4; ks++) {
            uint32_t vh[4][4], vl[4][4];
#pragma unroll
            for (int nh = 0; nh < 4; nh++) {
                const uint32_t ro = swz((uint32_t)(ks * 16) * 128 + lrow + nh * 32 + lseg);
                ldsm_x4_t(vh[nh], st + 8192  + ro);
                ldsm_x4_t(vl[nh], st + 16384 + ro);
            }
            uint32_t ah[4] = {pr0[2 * ks], pr8[2 * ks], pr0[2 * ks + 1], pr8[2 * ks + 1]};
            uint32_t al[4] = {qr0[2 * ks], qr8[2 * ks], qr0[2 * ks + 1], qr8[2 * ks + 1]};
#pragma unroll
            for (int nf = 0; nf < 8; nf++) {
                uint32_t b0 = vh[nf >> 1][(nf & 1) * 2];
                uint32_t b1 = vh[nf >> 1][(nf & 1) * 2 + 1];
                uint32_t c0 = vl[nf >> 1][(nf & 1) * 2];
                uint32_t c1 = vl[nf >> 1][(nf & 1) * 2 + 1];
                mma_bf16(o_acc[nf], ah, b0, b1);
                mma_bf16(o_acc[nf], ah, c0, c1);
                mma_bf16(o_acc[nf], al, b0, b1);
            }
        }
    }

    const float i0 = 1.f / l0, i8 = 1.f / l8;
    const int b = bh / HEADS, h = bh % HEADS;
    const int r0g = q0 + wid * 16 + (lid >> 2);
#pragma unroll
    for (int nf = 0; nf < 8; nf++) {
        const int d0 = nf * 8 + (lid & 3) * 2;
        float2 v0 = make_float2(rna_tf32(o_acc[nf][0] * i0), rna_tf32(o_acc[nf][1] * i0));
        float2 v1 = make_float2(rna_tf32(o_acc[nf][2] * i8), rna_tf32(o_acc[nf][3] * i8));
        *(float2*)(outf + (size_t)(b * S_LEN + r0g)     * EMBED + h * HDIM + d0) = v0;
        *(float2*)(outf + (size_t)(b * S_LEN + r0g + 8) * EMBED + h * HDIM + d0) = v1;
    }
}

// ---------------------------------------------------------------------------
extern "C" void kernel_launch(void* const* d_in, const int* in_sizes, int n_in,
                              void* d_out, int out_size)
{
    const float* X     = (const float*)d_in[0];
    const float* W_qkv = (const float*)d_in[3];
    const float* b_qkv = (const float*)d_in[4];
    const float* W_out = (const float*)d_in[5];
    const float* b_out = (const float*)d_in[6];
    float* out = (float*)d_out;

    float *wqr, *wor, *att;
    __nv_bfloat16 *Qb, *Kb, *Vh, *Vl;
    cudaGetSymbolAddress((void**)&wqr, g_wqr);
    cudaGetSymbolAddress((void**)&wor, g_wor);
    cudaGetSymbolAddress((void**)&att, g_att);
    cudaGetSymbolAddress((void**)&Qb,  g_Qb);
    cudaGetSymbolAddress((void**)&Kb,  g_Kb);
    cudaGetSymbolAddress((void**)&Vh,  g_Vh);
    cudaGetSymbolAddress((void**)&Vl,  g_Vl);

    cudaFuncSetAttribute(gemm_qkv_fused,
                         cudaFuncAttributeMaxDynamicSharedMemorySize, GEMM_SMEM);
    cudaFuncSetAttribute(gemm_tf32_mma,
                         cudaFuncAttributeMaxDynamicSharedMemorySize, GEMM_SMEM);
    cudaFuncSetAttribute(attn_tc,
                         cudaFuncAttributeMaxDynamicSharedMemorySize, ATT_SMEM);

    {   // tf32 pre-rounding (weights only)
        int n = N4_WQ + N4_WO;
        round_wts<<<(n + 255) / 256, 256>>>(W_qkv, wqr, W_out, wor);
    }
    {   // QKV projection, fused epilogue -> Qb/Kb/Vh/Vl
        dim3 grid(QKV_DIM / 128, MTOT / 256);
        gemm_qkv_fused<<<grid, 256, GEMM_SMEM>>>(X, wqr, b_qkv, Qb, Kb, Vh, Vl);
    }
    {   // tensor-core flash attention -> tf32-rounded fp32
        dim3 grid(S_LEN / 128, BATCH * HEADS);
        attn_tc<<<grid, 256, ATT_SMEM>>>(Qb, Kb, Vh, Vl, att);
    }
    {   // output projection
        dim3 grid(EMBED / 128, MTOT / 256);
        gemm_tf32_mma<<<grid, 256, GEMM_SMEM>>>(att, wor, b_out, out, EMBED);
    }
}